// round 6
// baseline (speedup 1.0000x reference)
#include <cuda_runtime.h>
#include <cuda_bf16.h>

typedef unsigned long long ull;
union F2 { float2 f; ull u; };
#define FMA2(c,a,b) asm("fma.rn.f32x2 %0, %1, %2, %0;" : "+l"(c) : "l"(a), "l"(b))

#define Bb 64
#define Tt 512
#define Hh 1024
#define G4 4096
#define HSEQ_N (Bb*Tt*Hh)

// scratch (device globals: allocation-free rule)
__device__ float g_xp[(size_t)Bb * Tt * G4];   // 512 MB x_proj
__device__ float g_h[2][Bb * Hh];              // double-buffered h
__device__ unsigned g_bar_count;
__device__ unsigned g_bar_gen;

// ===========================================================================
// Phase 1: g_xp[M=32768, 4096] = input[M,1024] @ Wi^T + b
// Tile 128x64x16, 256 threads, 32 outputs/thread, packed f32x2 FMA.
// ===========================================================================
#define PM 128
#define PN 64
#define PK 16

__global__ __launch_bounds__(256) void xproj_kernel(
    const float* __restrict__ A,
    const float* __restrict__ W0, const float* __restrict__ W1,
    const float* __restrict__ W2, const float* __restrict__ W3,
    const float* __restrict__ b0, const float* __restrict__ b1,
    const float* __restrict__ b2, const float* __restrict__ b3)
{
    __shared__ __align__(16) ull as_[2][PK][PM / 2];  // (A[2m],A[2m+1]) row pairs
    __shared__ __align__(16) ull bs_[2][PK][PN];      // (w,w) duplicated

    const int tid = threadIdx.x;
    const int nTile = blockIdx.x & 63;
    const int mTile = blockIdx.x >> 6;
    const int m0 = mTile * PM;
    const int n0 = nTile * PN;
    const int q = n0 >> 10;
    const float* W  = (q == 0) ? W0 : (q == 1) ? W1 : (q == 2) ? W2 : W3;
    const float* bb = (q == 0) ? b0 : (q == 1) ? b1 : (q == 2) ? b2 : b3;
    const int nq = n0 & 1023;

    const int ar = tid >> 1, ak = (tid & 1) * 8;
    const int wr = tid >> 2, wk = (tid & 3) * 4;
    const int tn = tid & 15, tm = tid >> 4;

    ull acc[4][4];
    #pragma unroll
    for (int i = 0; i < 4; i++)
        #pragma unroll
        for (int j = 0; j < 4; j++) acc[i][j] = 0ull;

    const float* Arow = A + (size_t)(m0 + ar) * 1024;
    const float* Wrow = W + (size_t)(nq + wr) * 1024;
    const int mp = ar >> 1, hl = ar & 1;

    {   // stage chunk 0
        float4 v0 = *(const float4*)(Arow + ak);
        float4 v1 = *(const float4*)(Arow + ak + 4);
        float4 w  = *(const float4*)(Wrow + wk);
        #pragma unroll
        for (int i = 0; i < 4; i++) {
            ((float*)&as_[0][ak + i][mp])[hl]     = (&v0.x)[i];
            ((float*)&as_[0][ak + 4 + i][mp])[hl] = (&v1.x)[i];
            F2 t; t.f = make_float2((&w.x)[i], (&w.x)[i]);
            bs_[0][wk + i][wr] = t.u;
        }
    }
    __syncthreads();

    int buf = 0;
    for (int ch = 0; ch < 64; ch++) {
        if (ch < 63) {
            const int k0 = (ch + 1) * PK;
            const int nb = buf ^ 1;
            float4 v0 = *(const float4*)(Arow + k0 + ak);
            float4 v1 = *(const float4*)(Arow + k0 + ak + 4);
            float4 w  = *(const float4*)(Wrow + k0 + wk);
            #pragma unroll
            for (int i = 0; i < 4; i++) {
                ((float*)&as_[nb][ak + i][mp])[hl]     = (&v0.x)[i];
                ((float*)&as_[nb][ak + 4 + i][mp])[hl] = (&v1.x)[i];
                F2 t; t.f = make_float2((&w.x)[i], (&w.x)[i]);
                bs_[nb][wk + i][wr] = t.u;
            }
        }
        #pragma unroll
        for (int kk = 0; kk < PK; kk++) {
            ulonglong2 a0 = *(const ulonglong2*)&as_[buf][kk][4 * tm];
            ulonglong2 a1 = *(const ulonglong2*)&as_[buf][kk][4 * tm + 2];
            ulonglong2 c0 = *(const ulonglong2*)&bs_[buf][kk][4 * tn];
            ulonglong2 c1 = *(const ulonglong2*)&bs_[buf][kk][4 * tn + 2];
            FMA2(acc[0][0], a0.x, c0.x); FMA2(acc[0][1], a0.x, c0.y);
            FMA2(acc[0][2], a0.x, c1.x); FMA2(acc[0][3], a0.x, c1.y);
            FMA2(acc[1][0], a0.y, c0.x); FMA2(acc[1][1], a0.y, c0.y);
            FMA2(acc[1][2], a0.y, c1.x); FMA2(acc[1][3], a0.y, c1.y);
            FMA2(acc[2][0], a1.x, c0.x); FMA2(acc[2][1], a1.x, c0.y);
            FMA2(acc[2][2], a1.x, c1.x); FMA2(acc[2][3], a1.x, c1.y);
            FMA2(acc[3][0], a1.y, c0.x); FMA2(acc[3][1], a1.y, c0.y);
            FMA2(acc[3][2], a1.y, c1.x); FMA2(acc[3][3], a1.y, c1.y);
        }
        __syncthreads();
        buf ^= 1;
    }

    float4 bv = *(const float4*)(bb + nq + 4 * tn);
    #pragma unroll
    for (int i = 0; i < 4; i++) {
        F2 u0, u1, u2, u3;
        u0.u = acc[i][0]; u1.u = acc[i][1]; u2.u = acc[i][2]; u3.u = acc[i][3];
        const int mA = m0 + (4 * tm + i) * 2;
        float4 r0 = make_float4(u0.f.x + bv.x, u1.f.x + bv.y, u2.f.x + bv.z, u3.f.x + bv.w);
        float4 r1 = make_float4(u0.f.y + bv.x, u1.f.y + bv.y, u2.f.y + bv.z, u3.f.y + bv.w);
        *(float4*)(g_xp + (size_t)mA * G4 + n0 + 4 * tn)       = r0;
        *(float4*)(g_xp + (size_t)(mA + 1) * G4 + n0 + 4 * tn) = r1;
    }
}

// ===========================================================================
// Phase 2: persistent scan. 128 CTAs x 256 thr.
// CTA owns 32 gate-rows (8 hidden x 4 gates); Wh slice SMEM-resident (packed
// k-pairs) for all 512 steps. Thread = (bg 0..7)x(rg 0..3)x(slice 0..7):
// 8 batches x 8 rows x 128 k's -> 64 ull accumulators, shuffle-reduced.
// ===========================================================================
#define WSR 34
#define HDR 66
#define SM_WS (512 * WSR * 8)       // 139264
#define SM_HD (2 * 64 * HDR * 8)    // 67584
#define SM_GB (64 * 33 * 4)         // 8448
#define SM_SCAN (SM_WS + SM_HD + SM_GB)

__device__ __forceinline__ float sigf(float x) { return 1.0f / (1.0f + __expf(-x)); }

__global__ __launch_bounds__(256, 1) void lstm_scan(
    const float* __restrict__ h0, const float* __restrict__ c0,
    const float* __restrict__ Whi, const float* __restrict__ Whf,
    const float* __restrict__ Whg, const float* __restrict__ Who,
    float* __restrict__ out)
{
    extern __shared__ char sm[];
    ull*   ws = (ull*)sm;                      // [512][WSR]: (w[r][2kp],w[r][2kp+1]) at [kp*WSR+r]
    ull*   hd = (ull*)(sm + SM_WS);            // [2][64][HDR]: (h[b][2kp],h[b][2kp+1])
    float* gb = (float*)(sm + SM_WS + SM_HD);  // [64][33] gate preacts

    const int tid = threadIdx.x;
    const int j0 = blockIdx.x * 8;
    const int sl = tid & 7;
    const int ow = tid >> 3;
    const int rg = ow & 3;
    const int bg = ow >> 2;

    // one-time: pack this CTA's 32 Wh rows into SMEM
    const float* Wm[4] = {Whi, Whf, Whg, Who};
    for (int r = 0; r < 32; r++) {
        const float* src = Wm[r >> 3] + (size_t)(j0 + (r & 7)) * Hh;
        for (int kp = tid; kp < 512; kp += 256) {
            F2 tt; tt.f = *(const float2*)(src + 2 * kp);
            ws[kp * WSR + r] = tt.u;
        }
    }

    const int rb = tid >> 2, rj = tid & 3;     // gate-phase mapping
    float cr0 = c0[rb * Hh + j0 + rj];
    float cr1 = c0[rb * Hh + j0 + rj + 4];
    __syncthreads();

    for (int t = 0; t < Tt; t++) {
        const float* hcur = (t == 0) ? h0 : g_h[t & 1];
        float* hnxt = g_h[(t + 1) & 1];

        // prefetch x_proj contributions for this thread's gate outputs
        float xq[2][4];
        {
            const float* xb = g_xp + ((size_t)rb * Tt + t) * G4;
            #pragma unroll
            for (int p = 0; p < 2; p++)
                #pragma unroll
                for (int q = 0; q < 4; q++)
                    xq[p][q] = xb[q * Hh + j0 + rj + 4 * p];
        }

        ull acc[8][8];
        #pragma unroll
        for (int j = 0; j < 8; j++)
            #pragma unroll
            for (int r = 0; r < 8; r++) acc[j][r] = 0ull;

        // stage chunk 0 (k 0..127), packed pairs, conflict-free STS.128
        #pragma unroll
        for (int u = 0; u < 8; u++) {
            int idx = u * 256 + tid;
            int b = idx >> 5, k4 = idx & 31;
            float4 v = *(const float4*)(hcur + b * Hh + k4 * 4);
            F2 t0, t1; t0.f = make_float2(v.x, v.y); t1.f = make_float2(v.z, v.w);
            ulonglong2 w2; w2.x = t0.u; w2.y = t1.u;
            *(ulonglong2*)(hd + b * HDR + k4 * 2) = w2;
        }
        __syncthreads();

        int buf = 0;
        for (int ch = 0; ch < 8; ch++) {
            if (ch < 7) {
                int nb = buf ^ 1;
                const float* hsrc = hcur + (ch + 1) * 128;
                #pragma unroll
                for (int u = 0; u < 8; u++) {
                    int idx = u * 256 + tid;
                    int b = idx >> 5, k4 = idx & 31;
                    float4 v = *(const float4*)(hsrc + b * Hh + k4 * 4);
                    F2 t0, t1; t0.f = make_float2(v.x, v.y); t1.f = make_float2(v.z, v.w);
                    ulonglong2 w2; w2.x = t0.u; w2.y = t1.u;
                    *(ulonglong2*)(hd + (nb * 64 + b) * HDR + k4 * 2) = w2;
                }
            }
            const ull* hb = hd + (size_t)buf * 64 * HDR + bg * 8 * HDR;
            const ull* wb = ws + (size_t)(ch * 64) * WSR + rg * 8;
            #pragma unroll
            for (int i = 0; i < 8; i++) {
                const int kl = i * 8 + sl;
                ulonglong2 wA = *(const ulonglong2*)(wb + kl * WSR);
                ulonglong2 wB = *(const ulonglong2*)(wb + kl * WSR + 2);
                ulonglong2 wC = *(const ulonglong2*)(wb + kl * WSR + 4);
                ulonglong2 wD = *(const ulonglong2*)(wb + kl * WSR + 6);
                ull hv[8];
                #pragma unroll
                for (int j = 0; j < 8; j++) hv[j] = hb[j * HDR + kl];
                #pragma unroll
                for (int j = 0; j < 8; j++) {
                    FMA2(acc[j][0], hv[j], wA.x); FMA2(acc[j][1], hv[j], wA.y);
                    FMA2(acc[j][2], hv[j], wB.x); FMA2(acc[j][3], hv[j], wB.y);
                    FMA2(acc[j][4], hv[j], wC.x); FMA2(acc[j][5], hv[j], wC.y);
                    FMA2(acc[j][6], hv[j], wD.x); FMA2(acc[j][7], hv[j], wD.y);
                }
            }
            __syncthreads();
            buf ^= 1;
        }

        // reduce 8 k-slices (intra-warp) + pair halves; slice 0 publishes
        #pragma unroll
        for (int j = 0; j < 8; j++)
            #pragma unroll
            for (int r = 0; r < 8; r++) {
                F2 u; u.u = acc[j][r];
                float v = u.f.x + u.f.y;
                v += __shfl_xor_sync(0xffffffffu, v, 1);
                v += __shfl_xor_sync(0xffffffffu, v, 2);
                v += __shfl_xor_sync(0xffffffffu, v, 4);
                if (sl == 0) gb[(bg * 8 + j) * 33 + rg * 8 + r] = v;
            }
        __syncthreads();

        // gates + state update (thread owns c for its 2 (b,j) cells)
        #pragma unroll
        for (int p = 0; p < 2; p++) {
            const int jj = rj + 4 * p;
            const float* gr = gb + rb * 33;
            float gi = gr[jj]      + xq[p][0];
            float gf = gr[8 + jj]  + xq[p][1];
            float gg = gr[16 + jj] + xq[p][2];
            float go = gr[24 + jj] + xq[p][3];
            float iv = sigf(gi), fv = sigf(gf), ov = sigf(go);
            float gv = 2.0f * sigf(2.0f * gg) - 1.0f;
            float cc = (p ? cr1 : cr0);
            cc = fv * cc + iv * gv;
            if (p) cr1 = cc; else cr0 = cc;
            float hv = ov * (2.0f * sigf(2.0f * cc) - 1.0f);
            hnxt[rb * Hh + j0 + jj] = hv;
            out[((size_t)rb * Tt + t) * Hh + j0 + jj] = hv;
            if (t == Tt - 1) {
                out[HSEQ_N + rb * Hh + j0 + jj] = hv;
                out[HSEQ_N + Bb * Hh + rb * Hh + j0 + jj] = cc;
            }
        }

        if (t < Tt - 1) {                       // grid barrier
            __syncthreads();
            if (tid == 0) {
                __threadfence();                 // drain h stores (gpu scope)
                unsigned g = *(volatile unsigned*)&g_bar_gen;
                if (atomicAdd(&g_bar_count, 1u) == gridDim.x - 1u) {
                    atomicExch(&g_bar_count, 0u);
                    __threadfence();
                    atomicAdd(&g_bar_gen, 1u);
                } else {
                    while (*(volatile unsigned*)&g_bar_gen == g) __nanosleep(64);
                }
                __threadfence();                 // acquire before reading new h
            }
            __syncthreads();
        }
    }
}

// ===========================================================================
extern "C" void kernel_launch(void* const* d_in, const int* in_sizes, int n_in,
                              void* d_out, int out_size)
{
    (void)in_sizes; (void)n_in; (void)out_size;
    const float* x   = (const float*)d_in[0];
    const float* h0  = (const float*)d_in[1];
    const float* c0  = (const float*)d_in[2];
    const float* Wii = (const float*)d_in[3];
    const float* Whi = (const float*)d_in[4];
    const float* bi  = (const float*)d_in[5];
    const float* Wif = (const float*)d_in[6];
    const float* Whf = (const float*)d_in[7];
    const float* bf  = (const float*)d_in[8];
    const float* Wig = (const float*)d_in[9];
    const float* Whg = (const float*)d_in[10];
    const float* bg_ = (const float*)d_in[11];
    const float* Wio = (const float*)d_in[12];
    const float* Who = (const float*)d_in[13];
    const float* bo  = (const float*)d_in[14];
    float* out = (float*)d_out;

    xproj_kernel<<<16384, 256>>>(x, Wii, Wif, Wig, Wio, bi, bf, bg_, bo);

    static int attr_done = 0;
    if (!attr_done) {
        cudaFuncSetAttribute(lstm_scan,
                             cudaFuncAttributeMaxDynamicSharedMemorySize, SM_SCAN);
        attr_done = 1;
    }
    lstm_scan<<<128, 256, SM_SCAN>>>(h0, c0, Whi, Whf, Whg, Who, out);
}